// round 1
// baseline (speedup 1.0000x reference)
#include <cuda_runtime.h>

// ---------------------------------------------------------------------------
// GraphSAGE(pool) x3 + BN + classifier, GB300 sm_103a
// Round 1: fp32 everywhere. FFMA2 (fma.rn.f32x2) GEMMs, CSR-based segment_max.
// ---------------------------------------------------------------------------

#define NNODES 100000
#define NEDGES 1000000
#define F      128
#define NCLS   16
#define NEG_SLOPE 0.01f
#define BN_EPS    1e-5f

// ------------------------------ scratch -----------------------------------
__device__ float g_hp [(size_t)NNODES * F];
__device__ float g_agg[(size_t)NNODES * F];
__device__ float g_h1 [(size_t)NNODES * F];
__device__ float g_h2 [(size_t)NNODES * F];
__device__ int   g_deg[NNODES];
__device__ int   g_rowptr[NNODES + 1];
__device__ int   g_cursor[NNODES];
__device__ int   g_col[NEDGES];
__device__ float g_sums[2 * F];

// --------------------------- f32x2 helpers --------------------------------
__device__ __forceinline__ void fma2(unsigned long long& d,
                                     unsigned long long a,
                                     unsigned long long b) {
    asm volatile("fma.rn.f32x2 %0, %1, %2, %0;" : "+l"(d) : "l"(a), "l"(b));
}
__device__ __forceinline__ unsigned long long pack2(float x, float y) {
    unsigned long long r;
    asm("mov.b64 %0, {%1, %2};" : "=l"(r) : "f"(x), "f"(y));
    return r;
}
__device__ __forceinline__ float2 unpack2(unsigned long long v) {
    float2 r;
    asm("mov.b64 {%0, %1}, %2;" : "=f"(r.x), "=f"(r.y) : "l"(v));
    return r;
}

// ------------------------------ CSR build ---------------------------------
__global__ void zero_prep() {
    int i = blockIdx.x * blockDim.x + threadIdx.x;
    if (i < NNODES) g_deg[i] = 0;
    if (i < 2 * F)  g_sums[i] = 0.f;
}

__global__ void deg_kernel(const int* __restrict__ dst) {
    int i = blockIdx.x * blockDim.x + threadIdx.x;
    if (i < NEDGES) atomicAdd(&g_deg[dst[i]], 1);
}

__global__ void scan_kernel() {
    __shared__ int sh[1024];
    int t = threadIdx.x;
    const int chunk = (NNODES + 1023) / 1024;   // 98
    int beg = t * chunk; if (beg > NNODES) beg = NNODES;
    int end = beg + chunk; if (end > NNODES) end = NNODES;
    int s = 0;
    for (int i = beg; i < end; i++) s += g_deg[i];
    sh[t] = s;
    __syncthreads();
    for (int off = 1; off < 1024; off <<= 1) {
        int v = (t >= off) ? sh[t - off] : 0;
        __syncthreads();
        sh[t] += v;
        __syncthreads();
    }
    int run = (t == 0) ? 0 : sh[t - 1];
    for (int i = beg; i < end; i++) {
        g_rowptr[i] = run;
        g_cursor[i] = run;
        run += g_deg[i];
    }
    if (t == 1023) g_rowptr[NNODES] = sh[1023];
}

__global__ void fill_kernel(const int* __restrict__ src,
                            const int* __restrict__ dst) {
    int i = blockIdx.x * blockDim.x + threadIdx.x;
    if (i < NEDGES) {
        int p = atomicAdd(&g_cursor[dst[i]], 1);
        g_col[p] = src[i];
    }
}

// ---------------------- segment-max aggregation ----------------------------
// One warp per destination node. hp >= 0 (post-relu), so 0-init max equals
// where(deg>0, segment_max, 0) exactly. hp table (51MB) is L2-resident.
__global__ void __launch_bounds__(256) agg_max(const float* __restrict__ hp,
                                               float* __restrict__ agg) {
    int warp = (blockIdx.x * blockDim.x + threadIdx.x) >> 5;
    int lane = threadIdx.x & 31;
    if (warp >= NNODES) return;
    int beg = g_rowptr[warp];
    int end = g_rowptr[warp + 1];
    float4 acc = make_float4(0.f, 0.f, 0.f, 0.f);
    const float4* hp4 = (const float4*)hp;
    for (int base = beg; base < end; base += 32) {
        int m = end - base; if (m > 32) m = 32;
        int idx = (lane < m) ? g_col[base + lane] : 0;
        for (int j = 0; j < m; j++) {
            int s = __shfl_sync(0xffffffffu, idx, j);
            float4 v = hp4[(size_t)s * 32 + lane];
            acc.x = fmaxf(acc.x, v.x);
            acc.y = fmaxf(acc.y, v.y);
            acc.z = fmaxf(acc.z, v.z);
            acc.w = fmaxf(acc.w, v.w);
        }
    }
    ((float4*)agg)[(size_t)warp * 32 + lane] = acc;
}

// ------------------------------- GEMM --------------------------------------
// C[n,128] = A@W (+ A2@W2) + bias, optional activation.
// Block tile: 64 rows x 128 cols, 256 threads, per-thread 4x8 via f32x2 pairs.
#define ACT_NONE  0
#define ACT_RELU  1
#define ACT_LEAKY 2
#define KK 32

__global__ void __launch_bounds__(256) gemm128(
    const float* __restrict__ A,  const float* __restrict__ W,
    const float* __restrict__ A2, const float* __restrict__ W2,
    const float* __restrict__ bias, float* __restrict__ C,
    int nRows, int act)
{
    __shared__ float w_s[KK][F];        // 16 KB
    __shared__ float a_s[KK][68];       // 8.5 KB, padded (stride 272B, 16B-mult)

    int tid  = threadIdx.x;
    int tx   = tid & 15;                // col group: cols [tx*8, tx*8+8)
    int ty   = tid >> 4;                // row group: rows [ty*4, ty*4+4)
    int row0 = blockIdx.x * 64;

    unsigned long long acc[4][4];
    #pragma unroll
    for (int r = 0; r < 4; r++)
        #pragma unroll
        for (int p = 0; p < 4; p++) acc[r][p] = 0ull;

    int nPass = (A2 != nullptr) ? 2 : 1;
    for (int pass = 0; pass < nPass; pass++) {
        const float* Ap = pass ? A2 : A;
        const float* Wp = pass ? W2 : W;
        for (int kc = 0; kc < F; kc += KK) {
            // stage weight chunk [KK][128]
            #pragma unroll
            for (int i = 0; i < 4; i++) {
                int li = tid + i * 256;          // float4 index 0..1023
                int k  = li >> 5;                // 32 float4 per row
                int c  = (li & 31) << 2;
                *(float4*)&w_s[k][c] = *(const float4*)&Wp[(kc + k) * F + c];
            }
            // stage A chunk transposed: a_s[k][row]
            #pragma unroll
            for (int i = 0; i < 2; i++) {
                int li = tid + i * 256;          // 0..511
                int r  = li & 63;
                int c4 = li >> 6;                // 0..7 (float4 within KK)
                int gr = row0 + r;
                float4 v = make_float4(0.f, 0.f, 0.f, 0.f);
                if (gr < nRows)
                    v = *(const float4*)&Ap[(size_t)gr * F + kc + c4 * 4];
                a_s[c4 * 4 + 0][r] = v.x;
                a_s[c4 * 4 + 1][r] = v.y;
                a_s[c4 * 4 + 2][r] = v.z;
                a_s[c4 * 4 + 3][r] = v.w;
            }
            __syncthreads();
            #pragma unroll
            for (int k = 0; k < KK; k++) {
                float4 av = *(const float4*)&a_s[k][ty * 4];
                ulonglong2 w01 = *(const ulonglong2*)&w_s[k][tx * 8];
                ulonglong2 w23 = *(const ulonglong2*)&w_s[k][tx * 8 + 4];
                unsigned long long aa;
                aa = pack2(av.x, av.x);
                fma2(acc[0][0], aa, w01.x); fma2(acc[0][1], aa, w01.y);
                fma2(acc[0][2], aa, w23.x); fma2(acc[0][3], aa, w23.y);
                aa = pack2(av.y, av.y);
                fma2(acc[1][0], aa, w01.x); fma2(acc[1][1], aa, w01.y);
                fma2(acc[1][2], aa, w23.x); fma2(acc[1][3], aa, w23.y);
                aa = pack2(av.z, av.z);
                fma2(acc[2][0], aa, w01.x); fma2(acc[2][1], aa, w01.y);
                fma2(acc[2][2], aa, w23.x); fma2(acc[2][3], aa, w23.y);
                aa = pack2(av.w, av.w);
                fma2(acc[3][0], aa, w01.x); fma2(acc[3][1], aa, w01.y);
                fma2(acc[3][2], aa, w23.x); fma2(acc[3][3], aa, w23.y);
            }
            __syncthreads();
        }
    }

    // epilogue
    #pragma unroll
    for (int r = 0; r < 4; r++) {
        int grow = row0 + ty * 4 + r;
        if (grow >= nRows) continue;
        float out[8];
        #pragma unroll
        for (int p = 0; p < 4; p++) {
            float2 v = unpack2(acc[r][p]);
            out[2 * p]     = v.x;
            out[2 * p + 1] = v.y;
        }
        #pragma unroll
        for (int j = 0; j < 8; j++) {
            float v = out[j] + bias[tx * 8 + j];
            if (act == ACT_RELU)       v = fmaxf(v, 0.f);
            else if (act == ACT_LEAKY) v = (v > 0.f) ? v : v * NEG_SLOPE;
            out[j] = v;
        }
        *(float4*)&C[(size_t)grow * F + tx * 8]     = make_float4(out[0], out[1], out[2], out[3]);
        *(float4*)&C[(size_t)grow * F + tx * 8 + 4] = make_float4(out[4], out[5], out[6], out[7]);
    }
}

// ------------------------------ BatchNorm ----------------------------------
__global__ void bn_stats(const float* __restrict__ X) {
    int col  = threadIdx.x & 127;
    int half = threadIdx.x >> 7;
    float s = 0.f, s2 = 0.f;
    for (int r = blockIdx.x * 2 + half; r < NNODES; r += gridDim.x * 2) {
        float v = X[(size_t)r * F + col];
        s += v; s2 += v * v;
    }
    __shared__ float sh[256], sh2[256];
    sh [threadIdx.x] = s;
    sh2[threadIdx.x] = s2;
    __syncthreads();
    if (half == 0) {
        s  = sh [col] + sh [col + 128];
        s2 = sh2[col] + sh2[col + 128];
        atomicAdd(&g_sums[col],     s);
        atomicAdd(&g_sums[F + col], s2);
    }
}

__global__ void bn_apply_leaky(float* __restrict__ X,
                               const float* __restrict__ gamma,
                               const float* __restrict__ beta) {
    __shared__ float scale[F], shift[F];
    if (threadIdx.x < F) {
        float mu  = g_sums[threadIdx.x] * (1.f / NNODES);
        float var = g_sums[F + threadIdx.x] * (1.f / NNODES) - mu * mu;
        float sc  = rsqrtf(var + BN_EPS) * gamma[threadIdx.x];
        scale[threadIdx.x] = sc;
        shift[threadIdx.x] = beta[threadIdx.x] - mu * sc;
    }
    __syncthreads();
    size_t total4 = (size_t)NNODES * 32;
    for (size_t i = blockIdx.x * blockDim.x + threadIdx.x; i < total4;
         i += (size_t)gridDim.x * blockDim.x) {
        int c = (int)(i & 31) * 4;
        float4 v = ((float4*)X)[i];
        v.x = v.x * scale[c]     + shift[c];
        v.y = v.y * scale[c + 1] + shift[c + 1];
        v.z = v.z * scale[c + 2] + shift[c + 2];
        v.w = v.w * scale[c + 3] + shift[c + 3];
        v.x = (v.x > 0.f) ? v.x : v.x * NEG_SLOPE;
        v.y = (v.y > 0.f) ? v.y : v.y * NEG_SLOPE;
        v.z = (v.z > 0.f) ? v.z : v.z * NEG_SLOPE;
        v.w = (v.w > 0.f) ? v.w : v.w * NEG_SLOPE;
        ((float4*)X)[i] = v;
    }
}

// ------------------------------ classifier ---------------------------------
__global__ void classifier(const float* __restrict__ H,
                           const float* __restrict__ wc,
                           const float* __restrict__ bc,
                           float* __restrict__ out) {
    __shared__ float w[F * NCLS];
    __shared__ float b[NCLS];
    for (int i = threadIdx.x; i < F * NCLS; i += blockDim.x) w[i] = wc[i];
    if (threadIdx.x < NCLS) b[threadIdx.x] = bc[threadIdx.x];
    __syncthreads();
    int r = blockIdx.x * blockDim.x + threadIdx.x;
    if (r >= NNODES) return;
    float acc[NCLS];
    #pragma unroll
    for (int j = 0; j < NCLS; j++) acc[j] = 0.f;
    for (int k = 0; k < F; k += 4) {
        float4 h4 = *(const float4*)&H[(size_t)r * F + k];
        #pragma unroll
        for (int j = 0; j < NCLS; j++)
            acc[j] += h4.x * w[k * NCLS + j] + h4.y * w[(k + 1) * NCLS + j]
                    + h4.z * w[(k + 2) * NCLS + j] + h4.w * w[(k + 3) * NCLS + j];
    }
    #pragma unroll
    for (int j = 0; j < NCLS; j++)
        out[(size_t)r * NCLS + j] = acc[j] + b[j];
}

// ------------------------------ launch -------------------------------------
extern "C" void kernel_launch(void* const* d_in, const int* in_sizes, int n_in,
                              void* d_out, int out_size) {
    const float* x    = (const float*)d_in[0];
    const int*   src  = (const int*)  d_in[1];
    const int*   dst  = (const int*)  d_in[2];
    const float* wp0  = (const float*)d_in[3];
    const float* bp0  = (const float*)d_in[4];
    const float* ws0  = (const float*)d_in[5];
    const float* wn0  = (const float*)d_in[6];
    const float* b0   = (const float*)d_in[7];
    const float* wp1  = (const float*)d_in[8];
    const float* bp1  = (const float*)d_in[9];
    const float* ws1  = (const float*)d_in[10];
    const float* wn1  = (const float*)d_in[11];
    const float* b1   = (const float*)d_in[12];
    const float* wp2  = (const float*)d_in[13];
    const float* bp2  = (const float*)d_in[14];
    const float* ws2  = (const float*)d_in[15];
    const float* wn2  = (const float*)d_in[16];
    const float* b2   = (const float*)d_in[17];
    const float* gam  = (const float*)d_in[18];
    const float* bet  = (const float*)d_in[19];
    const float* wc   = (const float*)d_in[20];
    const float* bc   = (const float*)d_in[21];
    float* out = (float*)d_out;

    float *hp, *agg, *h1, *h2;
    cudaGetSymbolAddress((void**)&hp,  g_hp);
    cudaGetSymbolAddress((void**)&agg, g_agg);
    cudaGetSymbolAddress((void**)&h1,  g_h1);
    cudaGetSymbolAddress((void**)&h2,  g_h2);

    const int gemmGrid = (NNODES + 63) / 64;       // 1563
    const int aggGrid  = (NNODES * 32 + 255) / 256; // warp/node, 8 warps/block
    const int edgeGrid = (NEDGES + 255) / 256;

    // CSR build (reused by all 3 layers)
    zero_prep<<<(NNODES + 255) / 256, 256>>>();
    deg_kernel<<<edgeGrid, 256>>>(dst);
    scan_kernel<<<1, 1024>>>();
    fill_kernel<<<edgeGrid, 256>>>(src, dst);

    // layer 0
    gemm128<<<gemmGrid, 256>>>(x, wp0, nullptr, nullptr, bp0, hp, NNODES, ACT_RELU);
    agg_max<<<aggGrid, 256>>>(hp, agg);
    gemm128<<<gemmGrid, 256>>>(x, ws0, agg, wn0, b0, h1, NNODES, ACT_LEAKY);

    // layer 1
    gemm128<<<gemmGrid, 256>>>(h1, wp1, nullptr, nullptr, bp1, hp, NNODES, ACT_RELU);
    agg_max<<<aggGrid, 256>>>(hp, agg);
    gemm128<<<gemmGrid, 256>>>(h1, ws1, agg, wn1, b1, h2, NNODES, ACT_NONE);
    bn_stats<<<512, 256>>>(h2);
    bn_apply_leaky<<<4096, 256>>>(h2, gam, bet);

    // layer 2
    gemm128<<<gemmGrid, 256>>>(h2, wp2, nullptr, nullptr, bp2, hp, NNODES, ACT_RELU);
    agg_max<<<aggGrid, 256>>>(hp, agg);
    gemm128<<<gemmGrid, 256>>>(h2, ws2, agg, wn2, b2, h1, NNODES, ACT_NONE);

    // classifier
    classifier<<<(NNODES + 255) / 256, 256>>>(h1, wc, bc, out);
}

// round 3
// speedup vs baseline: 1.9641x; 1.9641x over previous
#include <cuda_runtime.h>
#include <cuda_bf16.h>

// ---------------------------------------------------------------------------
// GraphSAGE(pool) x3 + BN + classifier — GB300 sm_103a
// Round 3: warp-level mma.sync bf16-split GEMMs (Ah*Wh + Ah*Wl + Al*Wh),
// fp32 storage everywhere else; CSR segment-max from round 1.
// (tcgen05 is unavailable: harness compiles via compute_103 PTX.)
// ---------------------------------------------------------------------------

#define NNODES 100000
#define NEDGES 1000000
#define F      128
#define NCLS   16
#define NEG_SLOPE 0.01f
#define BN_EPS    1e-5f
#define TILE_M 128
#define NTILES ((NNODES + TILE_M - 1) / TILE_M)   // 782

#define ACT_NONE  0
#define ACT_RELU  1
#define ACT_LEAKY 2

typedef unsigned int u32;
typedef unsigned long long u64;

// ------------------------------ scratch -----------------------------------
__device__ float g_hp [(size_t)NNODES * F];
__device__ float g_agg[(size_t)NNODES * F];
__device__ float g_h1 [(size_t)NNODES * F];
__device__ float g_h2 [(size_t)NNODES * F];
__device__ __align__(16) __nv_bfloat16 g_wth[9 * F * F];  // transposed [N,K] hi
__device__ __align__(16) __nv_bfloat16 g_wtl[9 * F * F];  // transposed [N,K] lo
__device__ int   g_deg[NNODES];
__device__ int   g_rowptr[NNODES + 1];
__device__ int   g_cursor[NNODES];
__device__ int   g_col[NEDGES];
__device__ float g_sums[2 * F];

// ------------------------------ helpers -----------------------------------
__device__ __forceinline__ u32 smem_u32(const void* p) {
    u32 a;
    asm("{ .reg .u64 t; cvta.to.shared.u64 t, %1; cvt.u32.u64 %0, t; }"
        : "=r"(a) : "l"(p));
    return a;
}

__device__ __forceinline__ void split_pair(float a, float b, u32& oh, u32& ol) {
    __nv_bfloat16 ha = __float2bfloat16(a), hb = __float2bfloat16(b);
    __nv_bfloat16 la = __float2bfloat16(a - __bfloat162float(ha));
    __nv_bfloat16 lb = __float2bfloat16(b - __bfloat162float(hb));
    oh = (u32)__bfloat16_as_ushort(ha) | ((u32)__bfloat16_as_ushort(hb) << 16);
    ol = (u32)__bfloat16_as_ushort(la) | ((u32)__bfloat16_as_ushort(lb) << 16);
}

__device__ __forceinline__ void ldm_x4(u32 addr, u32& r0, u32& r1, u32& r2, u32& r3) {
    asm volatile("ldmatrix.sync.aligned.m8n8.x4.shared.b16 {%0,%1,%2,%3}, [%4];"
                 : "=r"(r0), "=r"(r1), "=r"(r2), "=r"(r3) : "r"(addr));
}

__device__ __forceinline__ void mma16816(float* c, const u32* a, u32 b0, u32 b1) {
    asm volatile("mma.sync.aligned.m16n8k16.row.col.f32.bf16.bf16.f32 "
                 "{%0,%1,%2,%3}, {%4,%5,%6,%7}, {%8,%9}, {%0,%1,%2,%3};"
                 : "+f"(c[0]), "+f"(c[1]), "+f"(c[2]), "+f"(c[3])
                 : "r"(a[0]), "r"(a[1]), "r"(a[2]), "r"(a[3]), "r"(b0), "r"(b1));
}

// ------------------------------ CSR build ---------------------------------
__global__ void zero_prep() {
    int i = blockIdx.x * blockDim.x + threadIdx.x;
    if (i < NNODES) g_deg[i] = 0;
    if (i < 2 * F)  g_sums[i] = 0.f;
}

__global__ void deg_kernel(const int* __restrict__ dst) {
    int i = blockIdx.x * blockDim.x + threadIdx.x;
    if (i < NEDGES) atomicAdd(&g_deg[dst[i]], 1);
}

__global__ void scan_kernel() {
    __shared__ int sh[1024];
    int t = threadIdx.x;
    const int chunk = (NNODES + 1023) / 1024;
    int beg = t * chunk; if (beg > NNODES) beg = NNODES;
    int end = beg + chunk; if (end > NNODES) end = NNODES;
    int s = 0;
    for (int i = beg; i < end; i++) s += g_deg[i];
    sh[t] = s;
    __syncthreads();
    for (int off = 1; off < 1024; off <<= 1) {
        int v = (t >= off) ? sh[t - off] : 0;
        __syncthreads();
        sh[t] += v;
        __syncthreads();
    }
    int run = (t == 0) ? 0 : sh[t - 1];
    for (int i = beg; i < end; i++) {
        g_rowptr[i] = run;
        g_cursor[i] = run;
        run += g_deg[i];
    }
    if (t == 1023) g_rowptr[NNODES] = sh[1023];
}

__global__ void fill_kernel(const int* __restrict__ src,
                            const int* __restrict__ dst) {
    int i = blockIdx.x * blockDim.x + threadIdx.x;
    if (i < NEDGES) {
        int p = atomicAdd(&g_cursor[dst[i]], 1);
        g_col[p] = src[i];
    }
}

// ------------------------------ weight packing -----------------------------
// out[n*128+k] = split(W[k*128+n])   (transposed, bf16 hi/lo)
__global__ void pack_w(const float* __restrict__ W,
                       __nv_bfloat16* __restrict__ oh,
                       __nv_bfloat16* __restrict__ ol) {
    int e = blockIdx.x * blockDim.x + threadIdx.x;
    if (e >= F * F) return;
    int n = e >> 7, k = e & 127;
    float v = W[k * F + n];
    __nv_bfloat16 h = __float2bfloat16(v);
    __nv_bfloat16 l = __float2bfloat16(v - __bfloat162float(h));
    oh[e] = h;
    ol[e] = l;
}

// ---------------------- segment-max aggregation ----------------------------
// One warp per node. hp >= 0 (post-relu), so 0-init max equals
// where(deg>0, segment_max, 0) exactly.
__global__ void __launch_bounds__(256) agg_max(const float* __restrict__ hp,
                                               float* __restrict__ agg) {
    int warp = (blockIdx.x * blockDim.x + threadIdx.x) >> 5;
    int lane = threadIdx.x & 31;
    if (warp >= NNODES) return;
    int beg = g_rowptr[warp];
    int end = g_rowptr[warp + 1];
    float4 acc = make_float4(0.f, 0.f, 0.f, 0.f);
    const float4* hp4 = (const float4*)hp;
    for (int base = beg; base < end; base += 32) {
        int m = end - base; if (m > 32) m = 32;
        int idx = (lane < m) ? g_col[base + lane] : 0;
        for (int j = 0; j < m; j++) {
            int s = __shfl_sync(0xffffffffu, idx, j);
            float4 v = hp4[(size_t)s * 32 + lane];
            acc.x = fmaxf(acc.x, v.x);
            acc.y = fmaxf(acc.y, v.y);
            acc.z = fmaxf(acc.z, v.z);
            acc.w = fmaxf(acc.w, v.w);
        }
    }
    ((float4*)agg)[(size_t)warp * 32 + lane] = acc;
}

// ------------------------------- HMMA GEMM ---------------------------------
// C[nRows,128] = A@W (+ A2@W2) + bias, optional activation.
// A fp32 split to bf16 hi/lo during staging; W pre-split [N,K] bf16.
// SMEM rows 272B stride (256B payload + 16B pad): conflict-free ldmatrix.
#define RSTRIDE 272
#define TBYTES (128 * RSTRIDE)   // 34816

__global__ void __launch_bounds__(256, 1) mma_gemm(
    const float* __restrict__ A,
    const __nv_bfloat16* __restrict__ Wh, const __nv_bfloat16* __restrict__ Wl,
    const float* __restrict__ A2,
    const __nv_bfloat16* __restrict__ W2h, const __nv_bfloat16* __restrict__ W2l,
    const float* __restrict__ bias, float* __restrict__ C,
    int nRows, int act)
{
    extern __shared__ char dyn[];
    __shared__ float s_bias[F];
    u32 base = smem_u32(dyn);
    const u32 AH = base, AL = base + TBYTES, WH = base + 2 * TBYTES, WL = base + 3 * TBYTES;

    int tid  = threadIdx.x;
    int wid  = tid >> 5;
    int lane = tid & 31;
    int warp_m = wid & 3;    // 32-row slab
    int warp_n = wid >> 2;   // 64-col slab
    int row0 = blockIdx.x * TILE_M;

    if (tid < F) s_bias[tid] = bias[tid];

    float acc[2][8][4];
    #pragma unroll
    for (int mt = 0; mt < 2; mt++)
        #pragma unroll
        for (int nt = 0; nt < 8; nt++)
            #pragma unroll
            for (int q = 0; q < 4; q++) acc[mt][nt][q] = 0.f;

    // ldmatrix lane-address components (constant across k-steps)
    u32 a_row = (u32)(warp_m * 32) + (lane & 15);          // + mt*16
    u32 a_koff = (u32)(lane >> 4) * 16;
    u32 b_row = (u32)(warp_n * 64) + ((lane >> 4) & 1) * 8 + (lane & 7);  // + nt2*16
    u32 b_koff = (u32)((lane >> 3) & 1) * 16;

    int nPass = (A2 != nullptr) ? 2 : 1;
    for (int pass = 0; pass < nPass; pass++) {
        const float* Ap = pass ? A2 : A;
        const __nv_bfloat16* wh = pass ? W2h : Wh;
        const __nv_bfloat16* wl = pass ? W2l : Wl;

        if (pass) __syncthreads();   // all warps done reading previous tiles

        // stage A: fp32 -> bf16 hi/lo split
        #pragma unroll
        for (int i = 0; i < 8; i++) {
            int g = tid + i * 256;        // 0..2047
            int r = g >> 4;               // row 0..127
            int j = g & 15;               // 8-elem k-group
            int gr = row0 + r;
            float4 v0 = make_float4(0.f, 0.f, 0.f, 0.f), v1 = v0;
            if (gr < nRows) {
                const float4* ap4 = (const float4*)Ap;
                v0 = ap4[(size_t)gr * 32 + j * 2];
                v1 = ap4[(size_t)gr * 32 + j * 2 + 1];
            }
            uint4 hw, lw;
            split_pair(v0.x, v0.y, hw.x, lw.x);
            split_pair(v0.z, v0.w, hw.y, lw.y);
            split_pair(v1.x, v1.y, hw.z, lw.z);
            split_pair(v1.z, v1.w, hw.w, lw.w);
            u32 off = (u32)r * RSTRIDE + (u32)j * 16;
            asm volatile("st.shared.v4.b32 [%0], {%1,%2,%3,%4};"
                         :: "r"(AH + off), "r"(hw.x), "r"(hw.y), "r"(hw.z), "r"(hw.w) : "memory");
            asm volatile("st.shared.v4.b32 [%0], {%1,%2,%3,%4};"
                         :: "r"(AL + off), "r"(lw.x), "r"(lw.y), "r"(lw.z), "r"(lw.w) : "memory");
        }
        // stage W: straight bf16 copy (pre-split, [N=128, K=128])
        #pragma unroll
        for (int i = 0; i < 8; i++) {
            int g = tid + i * 256;
            int r = g >> 4;
            int j = g & 15;
            uint4 vh = ((const uint4*)wh)[r * 16 + j];
            uint4 vl = ((const uint4*)wl)[r * 16 + j];
            u32 off = (u32)r * RSTRIDE + (u32)j * 16;
            asm volatile("st.shared.v4.b32 [%0], {%1,%2,%3,%4};"
                         :: "r"(WH + off), "r"(vh.x), "r"(vh.y), "r"(vh.z), "r"(vh.w) : "memory");
            asm volatile("st.shared.v4.b32 [%0], {%1,%2,%3,%4};"
                         :: "r"(WL + off), "r"(vl.x), "r"(vl.y), "r"(vl.z), "r"(vl.w) : "memory");
        }
        __syncthreads();

        #pragma unroll
        for (int k16 = 0; k16 < 8; k16++) {
            u32 kbase = (u32)k16 * 32;
            u32 ah[2][4], al[2][4];
            #pragma unroll
            for (int mt = 0; mt < 2; mt++) {
                u32 off = (a_row + mt * 16) * RSTRIDE + kbase + a_koff;
                ldm_x4(AH + off, ah[mt][0], ah[mt][1], ah[mt][2], ah[mt][3]);
                ldm_x4(AL + off, al[mt][0], al[mt][1], al[mt][2], al[mt][3]);
            }
            u32 bh[8][2], bl[8][2];
            #pragma unroll
            for (int nt2 = 0; nt2 < 4; nt2++) {
                u32 off = (b_row + nt2 * 16) * RSTRIDE + kbase + b_koff;
                ldm_x4(WH + off, bh[2*nt2][0], bh[2*nt2][1], bh[2*nt2+1][0], bh[2*nt2+1][1]);
                ldm_x4(WL + off, bl[2*nt2][0], bl[2*nt2][1], bl[2*nt2+1][0], bl[2*nt2+1][1]);
            }
            #pragma unroll
            for (int mt = 0; mt < 2; mt++)
                #pragma unroll
                for (int nt = 0; nt < 8; nt++) {
                    mma16816(acc[mt][nt], ah[mt], bh[nt][0], bh[nt][1]);
                    mma16816(acc[mt][nt], ah[mt], bl[nt][0], bl[nt][1]);
                    mma16816(acc[mt][nt], al[mt], bh[nt][0], bh[nt][1]);
                }
        }
    }

    // epilogue: bias + activation + fp32 store
    int rbase = row0 + warp_m * 32 + (lane >> 2);
    int cbase = warp_n * 64 + (lane & 3) * 2;
    #pragma unroll
    for (int mt = 0; mt < 2; mt++) {
        #pragma unroll
        for (int half = 0; half < 2; half++) {
            int grow = rbase + mt * 16 + half * 8;
            if (grow >= nRows) continue;
            #pragma unroll
            for (int nt = 0; nt < 8; nt++) {
                int col = cbase + nt * 8;
                float v0 = acc[mt][nt][2 * half]     + s_bias[col];
                float v1 = acc[mt][nt][2 * half + 1] + s_bias[col + 1];
                if (act == ACT_RELU) {
                    v0 = fmaxf(v0, 0.f); v1 = fmaxf(v1, 0.f);
                } else if (act == ACT_LEAKY) {
                    v0 = (v0 > 0.f) ? v0 : v0 * NEG_SLOPE;
                    v1 = (v1 > 0.f) ? v1 : v1 * NEG_SLOPE;
                }
                *(float2*)&C[(size_t)grow * F + col] = make_float2(v0, v1);
            }
        }
    }
}

// ------------------------------ BatchNorm ----------------------------------
__global__ void bn_stats(const float* __restrict__ X) {
    int col  = threadIdx.x & 127;
    int half = threadIdx.x >> 7;
    float s = 0.f, s2 = 0.f;
    for (int r = blockIdx.x * 2 + half; r < NNODES; r += gridDim.x * 2) {
        float v = X[(size_t)r * F + col];
        s += v; s2 += v * v;
    }
    __shared__ float sh[256], sh2[256];
    sh [threadIdx.x] = s;
    sh2[threadIdx.x] = s2;
    __syncthreads();
    if (half == 0) {
        s  = sh [col] + sh [col + 128];
        s2 = sh2[col] + sh2[col + 128];
        atomicAdd(&g_sums[col],     s);
        atomicAdd(&g_sums[F + col], s2);
    }
}

__global__ void bn_apply_leaky(float* __restrict__ X,
                               const float* __restrict__ gamma,
                               const float* __restrict__ beta) {
    __shared__ float scale[F], shift[F];
    if (threadIdx.x < F) {
        float mu  = g_sums[threadIdx.x] * (1.f / NNODES);
        float var = g_sums[F + threadIdx.x] * (1.f / NNODES) - mu * mu;
        float sc  = rsqrtf(var + BN_EPS) * gamma[threadIdx.x];
        scale[threadIdx.x] = sc;
        shift[threadIdx.x] = beta[threadIdx.x] - mu * sc;
    }
    __syncthreads();
    size_t total4 = (size_t)NNODES * 32;
    for (size_t i = blockIdx.x * blockDim.x + threadIdx.x; i < total4;
         i += (size_t)gridDim.x * blockDim.x) {
        int c = (int)(i & 31) * 4;
        float4 v = ((float4*)X)[i];
        v.x = v.x * scale[c]     + shift[c];
        v.y = v.y * scale[c + 1] + shift[c + 1];
        v.z = v.z * scale[c + 2] + shift[c + 2];
        v.w = v.w * scale[c + 3] + shift[c + 3];
        v.x = (v.x > 0.f) ? v.x : v.x * NEG_SLOPE;
        v.y = (v.y > 0.f) ? v.y : v.y * NEG_SLOPE;
        v.z = (v.z > 0.f) ? v.z : v.z * NEG_SLOPE;
        v.w = (v.w > 0.f) ? v.w : v.w * NEG_SLOPE;
        ((float4*)X)[i] = v;
    }
}

// ------------------------------ classifier ---------------------------------
__global__ void classifier(const float* __restrict__ H,
                           const float* __restrict__ wc,
                           const float* __restrict__ bc,
                           float* __restrict__ out) {
    __shared__ float w[F * NCLS];
    __shared__ float b[NCLS];
    for (int i = threadIdx.x; i < F * NCLS; i += blockDim.x) w[i] = wc[i];
    if (threadIdx.x < NCLS) b[threadIdx.x] = bc[threadIdx.x];
    __syncthreads();
    int r = blockIdx.x * blockDim.x + threadIdx.x;
    if (r >= NNODES) return;
    float acc[NCLS];
    #pragma unroll
    for (int j = 0; j < NCLS; j++) acc[j] = 0.f;
    for (int k = 0; k < F; k += 4) {
        float4 h4 = *(const float4*)&H[(size_t)r * F + k];
        #pragma unroll
        for (int j = 0; j < NCLS; j++)
            acc[j] += h4.x * w[k * NCLS + j] + h4.y * w[(k + 1) * NCLS + j]
                    + h4.z * w[(k + 2) * NCLS + j] + h4.w * w[(k + 3) * NCLS + j];
    }
    #pragma unroll
    for (int j = 0; j < NCLS; j++)
        out[(size_t)r * NCLS + j] = acc[j] + b[j];
}

// ------------------------------ launch -------------------------------------
extern "C" void kernel_launch(void* const* d_in, const int* in_sizes, int n_in,
                              void* d_out, int out_size) {
    const float* x   = (const float*)d_in[0];
    const int*   src = (const int*)  d_in[1];
    const int*   dst = (const int*)  d_in[2];
    const float* wp[3] = { (const float*)d_in[3], (const float*)d_in[8],  (const float*)d_in[13] };
    const float* bp[3] = { (const float*)d_in[4], (const float*)d_in[9],  (const float*)d_in[14] };
    const float* ws[3] = { (const float*)d_in[5], (const float*)d_in[10], (const float*)d_in[15] };
    const float* wn[3] = { (const float*)d_in[6], (const float*)d_in[11], (const float*)d_in[16] };
    const float* bb[3] = { (const float*)d_in[7], (const float*)d_in[12], (const float*)d_in[17] };
    const float* gam = (const float*)d_in[18];
    const float* bet = (const float*)d_in[19];
    const float* wc  = (const float*)d_in[20];
    const float* bc  = (const float*)d_in[21];
    float* out = (float*)d_out;

    float *hp, *agg, *h1, *h2;
    __nv_bfloat16 *wth, *wtl;
    cudaGetSymbolAddress((void**)&hp,  g_hp);
    cudaGetSymbolAddress((void**)&agg, g_agg);
    cudaGetSymbolAddress((void**)&h1,  g_h1);
    cudaGetSymbolAddress((void**)&h2,  g_h2);
    cudaGetSymbolAddress((void**)&wth, g_wth);
    cudaGetSymbolAddress((void**)&wtl, g_wtl);

    const int SMEM_DYN = 4 * TBYTES;   // 139264
    cudaFuncSetAttribute(mma_gemm, cudaFuncAttributeMaxDynamicSharedMemorySize, SMEM_DYN);

    const int edgeGrid = (NEDGES + 255) / 256;
    const int aggGrid  = (NNODES * 32 + 255) / 256;
    const int FF = F * F;

    // CSR build (shared by all 3 layers)
    zero_prep<<<(NNODES + 255) / 256, 256>>>();
    deg_kernel<<<edgeGrid, 256>>>(dst);
    scan_kernel<<<1, 1024>>>();
    fill_kernel<<<edgeGrid, 256>>>(src, dst);

    // pack weights: slot 3i=wp, 3i+1=ws, 3i+2=wn  (transposed + split)
    for (int i = 0; i < 3; i++) {
        pack_w<<<64, 256>>>(wp[i], wth + (3*i)     * FF, wtl + (3*i)     * FF);
        pack_w<<<64, 256>>>(ws[i], wth + (3*i + 1) * FF, wtl + (3*i + 1) * FF);
        pack_w<<<64, 256>>>(wn[i], wth + (3*i + 2) * FF, wtl + (3*i + 2) * FF);
    }

    const float* hin = x;
    float* hout[3] = { h1, h2, h1 };
    int actOut[3] = { ACT_LEAKY, ACT_NONE, ACT_NONE };

    for (int i = 0; i < 3; i++) {
        // hp = relu(h @ wp + bp)
        mma_gemm<<<NTILES, 256, SMEM_DYN>>>(
            hin, wth + (3*i) * FF, wtl + (3*i) * FF,
            nullptr, nullptr, nullptr,
            bp[i], hp, NNODES, ACT_RELU);
        // agg = segment_max(hp[src] -> dst)
        agg_max<<<aggGrid, 256>>>(hp, agg);
        // h' = h @ ws + agg @ wn + b
        mma_gemm<<<NTILES, 256, SMEM_DYN>>>(
            hin, wth + (3*i + 1) * FF, wtl + (3*i + 1) * FF,
            agg, wth + (3*i + 2) * FF, wtl + (3*i + 2) * FF,
            bb[i], hout[i], NNODES, actOut[i]);
        if (i == 1) {
            bn_stats<<<512, 256>>>(h2);
            bn_apply_leaky<<<4096, 256>>>(h2, gam, bet);
        }
        hin = hout[i];
    }

    classifier<<<(NNODES + 255) / 256, 256>>>(h1, wc, bc, out);
}